// round 8
// baseline (speedup 1.0000x reference)
#include <cuda_runtime.h>

#define BATCH 4
#define NQ    64
#define SEQ   1024
#define HIDD  512
#define QKD   512

// Scratch (no allocation allowed -> __device__ globals)
__device__ float g_kproj[BATCH * SEQ * HIDD];   // 8 MB
__device__ float g_qproj[BATCH * NQ  * HIDD];   // 512 KB
__device__ float g_attn [BATCH * NQ  * SEQ];    // 1 MB (raw scores, then softmaxed in place)

// ---------------------------------------------------------------------------
// helpers: packed f32x2 FMA + fast tanh
// ---------------------------------------------------------------------------
__device__ __forceinline__ unsigned long long pack2(float lo, float hi) {
    unsigned long long r;
    asm("mov.b64 %0, {%1,%2};" : "=l"(r) : "f"(lo), "f"(hi));
    return r;
}
__device__ __forceinline__ float2 unpack2(unsigned long long v) {
    float2 f;
    asm("mov.b64 {%0,%1}, %2;" : "=f"(f.x), "=f"(f.y) : "l"(v));
    return f;
}
__device__ __forceinline__ void fma2(unsigned long long& d,
                                     unsigned long long a,
                                     unsigned long long b) {
    asm("fma.rn.f32x2 %0, %1, %2, %0;" : "+l"(d) : "l"(a), "l"(b));
}
__device__ __forceinline__ float fast_tanh(float x) {
    float y;
    asm("tanh.approx.f32 %0, %1;" : "=f"(y) : "f"(x));
    return y;
}

// ---------------------------------------------------------------------------
// Projection GEMM: C[m,n] = sum_d A[m,d] * W[n, woff+d]  (+ bias[n])
// A row-major [M, lda], W row-major [N, ldw]. TM=4, TN=8 fixed.
// sel==0 -> C = g_kproj, sel==1 -> C = g_qproj.
// ---------------------------------------------------------------------------
template <int BM, int BN>
__global__ void proj_gemm(const float* __restrict__ A, int lda,
                          const float* __restrict__ W, int ldw, int woff,
                          const float* __restrict__ bias,
                          int N, int K, int sel)
{
    constexpr int BK = 16;
    constexpr int TM = 4;
    constexpr int TN = 8;
    constexpr int TX = BN / TN;          // threads in n
    constexpr int TY = BM / TM;          // threads in m
    constexpr int NT = TX * TY;

    __shared__ float As[BK][BM + 4];     // [k][m]
    __shared__ float Ws[BK][BN + 4];     // [k][n]

    float* C = sel ? g_qproj : g_kproj;

    const int tid = threadIdx.x;
    const int tx  = tid % TX;
    const int ty  = tid / TX;
    const int m0  = blockIdx.y * BM;
    const int n0  = blockIdx.x * BN;

    unsigned long long acc[TM][TN / 2];
    #pragma unroll
    for (int i = 0; i < TM; ++i)
        #pragma unroll
        for (int j = 0; j < TN / 2; ++j) acc[i][j] = 0ull;

    constexpr int A_LD4 = BM * BK / 4;
    constexpr int W_LD4 = BN * BK / 4;

    for (int k0 = 0; k0 < K; k0 += BK) {
        #pragma unroll
        for (int l = 0; l < A_LD4 / NT; ++l) {
            int idx = tid + l * NT;
            int row = idx / (BK / 4);
            int c4  = idx % (BK / 4);
            float4 v = *(const float4*)&A[(m0 + row) * lda + k0 + c4 * 4];
            As[c4 * 4 + 0][row] = v.x;
            As[c4 * 4 + 1][row] = v.y;
            As[c4 * 4 + 2][row] = v.z;
            As[c4 * 4 + 3][row] = v.w;
        }
        #pragma unroll
        for (int l = 0; l < W_LD4 / NT; ++l) {
            int idx = tid + l * NT;
            int row = idx / (BK / 4);
            int c4  = idx % (BK / 4);
            float4 v = *(const float4*)&W[(n0 + row) * ldw + woff + k0 + c4 * 4];
            Ws[c4 * 4 + 0][row] = v.x;
            Ws[c4 * 4 + 1][row] = v.y;
            Ws[c4 * 4 + 2][row] = v.z;
            Ws[c4 * 4 + 3][row] = v.w;
        }
        __syncthreads();

        #pragma unroll
        for (int dk = 0; dk < BK; ++dk) {
            float4 a4 = *(const float4*)&As[dk][ty * TM];
            float4 w0 = *(const float4*)&Ws[dk][tx * TN];
            float4 w1 = *(const float4*)&Ws[dk][tx * TN + 4];

            unsigned long long am[4] = {
                pack2(a4.x, a4.x), pack2(a4.y, a4.y),
                pack2(a4.z, a4.z), pack2(a4.w, a4.w)
            };
            unsigned long long wp[4] = {
                pack2(w0.x, w0.y), pack2(w0.z, w0.w),
                pack2(w1.x, w1.y), pack2(w1.z, w1.w)
            };
            #pragma unroll
            for (int i = 0; i < 4; ++i)
                #pragma unroll
                for (int j = 0; j < 4; ++j)
                    fma2(acc[i][j], am[i], wp[j]);
        }
        __syncthreads();
    }

    #pragma unroll
    for (int i = 0; i < TM; ++i) {
        int m = m0 + ty * TM + i;
        #pragma unroll
        for (int j = 0; j < TN / 2; ++j) {
            int n = n0 + tx * TN + 2 * j;
            float2 v = unpack2(acc[i][j]);
            if (bias) { v.x += bias[n]; v.y += bias[n + 1]; }
            *(float2*)&C[m * N + n] = v;
        }
    }
}

// ---------------------------------------------------------------------------
// Scores: g_attn[b,q,s] = sum_h tanh(qproj[b,q,h] + kproj[b,s,h]) * w2[h]
// Block tile: 32 q x 32 s, 128 threads (8 tq x 16 ts), micro 4q x 2s.
// h chunked by 64 through smem. MUFU-bound by design.
// ---------------------------------------------------------------------------
__global__ void scores_kernel(const float* __restrict__ w2)
{
    constexpr int QT = 32, ST = 32, HT = 64;
    __shared__ float qs[HT][QT];   // [h][q]
    __shared__ float ks[HT][ST];   // [h][s]
    __shared__ float w2s[HT];

    const int b  = blockIdx.z;
    const int q0 = blockIdx.y * QT;
    const int s0 = blockIdx.x * ST;
    const int tid = threadIdx.x;      // 128
    const int ts = tid % 16;
    const int tq = tid / 16;

    float acc[4][2] = {};

    for (int h0 = 0; h0 < HIDD; h0 += HT) {
        #pragma unroll
        for (int l = 0; l < 4; ++l) {
            int idx = tid + l * 128;           // 512 float4
            int q   = idx / 16;                // 16 float4 per q row (64 h)
            int c4  = idx % 16;
            float4 v = *(const float4*)&g_qproj[(b * NQ + q0 + q) * HIDD + h0 + c4 * 4];
            qs[c4 * 4 + 0][q] = v.x;
            qs[c4 * 4 + 1][q] = v.y;
            qs[c4 * 4 + 2][q] = v.z;
            qs[c4 * 4 + 3][q] = v.w;
        }
        #pragma unroll
        for (int l = 0; l < 4; ++l) {
            int idx = tid + l * 128;
            int s   = idx / 16;
            int c4  = idx % 16;
            float4 v = *(const float4*)&g_kproj[(b * SEQ + s0 + s) * HIDD + h0 + c4 * 4];
            ks[c4 * 4 + 0][s] = v.x;
            ks[c4 * 4 + 1][s] = v.y;
            ks[c4 * 4 + 2][s] = v.z;
            ks[c4 * 4 + 3][s] = v.w;
        }
        if (tid < HT) w2s[tid] = w2[h0 + tid];
        __syncthreads();

        #pragma unroll 4
        for (int h = 0; h < HT; ++h) {
            float4 a = *(const float4*)&qs[h][tq * 4];
            float2 k = *(const float2*)&ks[h][ts * 2];
            float  wv = w2s[h];
            float aa[4] = {a.x, a.y, a.z, a.w};
            float kv[2] = {k.x, k.y};
            #pragma unroll
            for (int i = 0; i < 4; ++i)
                #pragma unroll
                for (int j = 0; j < 2; ++j)
                    acc[i][j] += fast_tanh(aa[i] + kv[j]) * wv;
        }
        __syncthreads();
    }

    #pragma unroll
    for (int i = 0; i < 4; ++i) {
        int q = q0 + tq * 4 + i;
        float2 o = {acc[i][0], acc[i][1]};
        *(float2*)&g_attn[(b * NQ + q) * SEQ + s0 + ts * 2] = o;
    }
}

// ---------------------------------------------------------------------------
// Softmax over s (in place on g_attn). One block per (b,q) row.
// ---------------------------------------------------------------------------
__global__ void softmax_kernel()
{
    const int row = blockIdx.x;           // 0..255
    float* p = &g_attn[row * SEQ];
    const int tid = threadIdx.x;          // 128, 8 elems each
    __shared__ float red[128];

    float4 a = *(const float4*)&p[tid * 8];
    float4 c = *(const float4*)&p[tid * 8 + 4];

    float m = fmaxf(fmaxf(fmaxf(a.x, a.y), fmaxf(a.z, a.w)),
                    fmaxf(fmaxf(c.x, c.y), fmaxf(c.z, c.w)));
    red[tid] = m;
    __syncthreads();
    #pragma unroll
    for (int off = 64; off > 0; off >>= 1) {
        if (tid < off) red[tid] = fmaxf(red[tid], red[tid + off]);
        __syncthreads();
    }
    float rowmax = red[0];
    __syncthreads();

    a.x = __expf(a.x - rowmax); a.y = __expf(a.y - rowmax);
    a.z = __expf(a.z - rowmax); a.w = __expf(a.w - rowmax);
    c.x = __expf(c.x - rowmax); c.y = __expf(c.y - rowmax);
    c.z = __expf(c.z - rowmax); c.w = __expf(c.w - rowmax);

    float s = a.x + a.y + a.z + a.w + c.x + c.y + c.z + c.w;
    red[tid] = s;
    __syncthreads();
    #pragma unroll
    for (int off = 64; off > 0; off >>= 1) {
        if (tid < off) red[tid] += red[tid + off];
        __syncthreads();
    }
    float inv = 1.0f / red[0];

    a.x *= inv; a.y *= inv; a.z *= inv; a.w *= inv;
    c.x *= inv; c.y *= inv; c.z *= inv; c.w *= inv;
    *(float4*)&p[tid * 8]     = a;
    *(float4*)&p[tid * 8 + 4] = c;
}

// ---------------------------------------------------------------------------
// Final: out[b,q,v] = sum_s attn[b,q,s] * values[b,s,v]
// Block: all 64 q x 16 v-cols, 256 threads (8 tx x 32 ty), micro 2q x 2v.
// ---------------------------------------------------------------------------
__global__ void final_kernel(const float* __restrict__ values,
                             float* __restrict__ out)
{
    constexpr int VT = 16, SC = 32;
    __shared__ float at[SC][NQ];      // [s][q]
    __shared__ float vs[SC][VT];      // [s][v]

    const int b  = blockIdx.y;
    const int v0 = blockIdx.x * VT;
    const int tid = threadIdx.x;      // 256
    const int tx = tid % 8;
    const int ty = tid / 8;

    float acc[2][2] = {};

    for (int s0 = 0; s0 < SEQ; s0 += SC) {
        #pragma unroll
        for (int l = 0; l < 2; ++l) {
            int idx = tid + l * 256;          // 512 float4
            int q   = idx / 8;                // 8 float4 per q row (32 s)
            int c4  = idx % 8;
            float4 v = *(const float4*)&g_attn[(b * NQ + q) * SEQ + s0 + c4 * 4];
            at[c4 * 4 + 0][q] = v.x;
            at[c4 * 4 + 1][q] = v.y;
            at[c4 * 4 + 2][q] = v.z;
            at[c4 * 4 + 3][q] = v.w;
        }
        if (tid < 128) {
            int s  = tid / 4;
            int c4 = tid % 4;
            float4 v = *(const float4*)&values[(b * SEQ + s0 + s) * 512 + v0 + c4 * 4];
            *(float4*)&vs[s][c4 * 4] = v;
        }
        __syncthreads();

        #pragma unroll 8
        for (int s = 0; s < SC; ++s) {
            float2 a = *(const float2*)&at[s][ty * 2];
            float2 v = *(const float2*)&vs[s][tx * 2];
            acc[0][0] += a.x * v.x;  acc[0][1] += a.x * v.y;
            acc[1][0] += a.y * v.x;  acc[1][1] += a.y * v.y;
        }
        __syncthreads();
    }

    #pragma unroll
    for (int i = 0; i < 2; ++i) {
        int q = ty * 2 + i;
        float2 o = {acc[i][0], acc[i][1]};
        *(float2*)&out[(b * NQ + q) * 512 + v0 + tx * 2] = o;
    }
}

// ---------------------------------------------------------------------------
extern "C" void kernel_launch(void* const* d_in, const int* in_sizes, int n_in,
                              void* d_out, int out_size)
{
    (void)in_sizes; (void)n_in; (void)out_size;
    const float* queries = (const float*)d_in[0];   // (4,64,512)
    const float* keys    = (const float*)d_in[1];   // (4,1024,512)
    const float* values  = (const float*)d_in[2];   // (4,1024,512)
    const float* W1      = (const float*)d_in[3];   // (512,1024)
    const float* b1      = (const float*)d_in[4];   // (512,)
    const float* w2      = (const float*)d_in[5];   // (512,)
    float* out = (float*)d_out;                     // (4,64,512)

    // k_proj = keys @ W1[:,512:].T + b1  -> g_kproj   (M=4096, N=512, K=512)
    proj_gemm<64, 128><<<dim3(512 / 128, (BATCH * SEQ) / 64), 256>>>(
        keys, QKD, W1, QKD * 2, QKD, b1, HIDD, QKD, /*sel=*/0);

    // q_proj = queries @ W1[:,:512].T   -> g_qproj   (M=256, N=512, K=512)
    proj_gemm<32, 64><<<dim3(512 / 64, (BATCH * NQ) / 32), 64>>>(
        queries, QKD, W1, QKD * 2, 0, nullptr, HIDD, QKD, /*sel=*/1);

    // scores -> g_attn
    scores_kernel<<<dim3(SEQ / 32, NQ / 32, BATCH), 128>>>(w2);

    // softmax in place
    softmax_kernel<<<BATCH * NQ, 128>>>();

    // out = attn @ values
    final_kernel<<<dim3(512 / 16, BATCH), 256>>>(values, out);
}

// round 16
// speedup vs baseline: 1.7159x; 1.7159x over previous
#include <cuda_runtime.h>
#include <cuda_bf16.h>
#include <cstdint>

#define BATCH 4
#define NQ    64
#define SEQ   1024
#define HIDD  512
#define QKD   512

#define MROWS (BATCH * SEQ + BATCH * NQ)   // 4352 = 34 * 128
#define KC 64                               // k elems per smem chunk
#define NCHUNK 24                           // 1536 / 64
#define CHUNK_BYTES 16384                   // 128 rows x 64 bf16 x 2B

// ---------------------------------------------------------------------------
// Scratch (__device__ globals; no allocation allowed)
// ---------------------------------------------------------------------------
__device__ __nv_bfloat16 g_abf [MROWS * 1024];   // [hi(512) | lo(512)] per row (keys then queries)
__device__ __nv_bfloat16 g_wkbf[HIDD * 1024];    // W1[:,512:] split
__device__ __nv_bfloat16 g_wqbf[HIDD * 1024];    // W1[:,:512] split
__device__ float g_kproj[BATCH * SEQ * HIDD];    // 8 MB
__device__ float g_qproj[BATCH * NQ  * HIDD];    // 512 KB
__device__ float g_attn [BATCH * NQ  * SEQ];     // 1 MB

// ---------------------------------------------------------------------------
// PTX helpers (all compute_80-safe; NO tcgen05 — ptxas target is sm_103 non-'a')
// ---------------------------------------------------------------------------
__device__ __forceinline__ uint32_t smem_u32(const void* p) {
    uint32_t a;
    asm("{ .reg .u64 t; cvta.to.shared.u64 t, %1; cvt.u32.u64 %0, t; }"
        : "=r"(a) : "l"(p));
    return a;
}
__device__ __forceinline__ void cp16(uint32_t s, const void* g) {
    asm volatile("cp.async.cg.shared.global [%0], [%1], 16;" :: "r"(s), "l"(g) : "memory");
}
__device__ __forceinline__ void cp_commit() {
    asm volatile("cp.async.commit_group;" ::: "memory");
}
__device__ __forceinline__ void ldm4(uint32_t* r, uint32_t addr) {
    asm volatile("ldmatrix.sync.aligned.m8n8.x4.shared.b16 {%0,%1,%2,%3}, [%4];"
                 : "=r"(r[0]), "=r"(r[1]), "=r"(r[2]), "=r"(r[3]) : "r"(addr));
}
__device__ __forceinline__ void mma16816(float* c,
                                         uint32_t a0, uint32_t a1, uint32_t a2, uint32_t a3,
                                         uint32_t b0, uint32_t b1) {
    asm volatile(
        "mma.sync.aligned.m16n8k16.row.col.f32.bf16.bf16.f32 "
        "{%0,%1,%2,%3}, {%4,%5,%6,%7}, {%8,%9}, {%0,%1,%2,%3};"
        : "+f"(c[0]), "+f"(c[1]), "+f"(c[2]), "+f"(c[3])
        : "r"(a0), "r"(a1), "r"(a2), "r"(a3), "r"(b0), "r"(b1));
}
__device__ __forceinline__ float fast_tanh(float x) {
    float y;
    asm("tanh.approx.f32 %0, %1;" : "=f"(y) : "f"(x));
    return y;
}

// ---------------------------------------------------------------------------
// Prep: split fp32 -> (bf16 hi, bf16 lo) for A (keys||queries) and W slices.
// ---------------------------------------------------------------------------
__device__ __forceinline__ void split4(const float4 x, __nv_bfloat16* hip, __nv_bfloat16* lop) {
    float xs[4] = {x.x, x.y, x.z, x.w};
    uint32_t uh[2] = {0, 0}, ul[2] = {0, 0};
    #pragma unroll
    for (int i = 0; i < 4; ++i) {
        __nv_bfloat16 h = __float2bfloat16(xs[i]);
        __nv_bfloat16 l = __float2bfloat16(xs[i] - __bfloat162float(h));
        uh[i / 2] |= (uint32_t)__bfloat16_as_ushort(h) << ((i & 1) * 16);
        ul[i / 2] |= (uint32_t)__bfloat16_as_ushort(l) << ((i & 1) * 16);
    }
    *(uint2*)hip = make_uint2(uh[0], uh[1]);
    *(uint2*)lop = make_uint2(ul[0], ul[1]);
}

__global__ void prep_convert(const float* __restrict__ queries,
                             const float* __restrict__ keys,
                             const float* __restrict__ W1)
{
    const int NA = MROWS * (QKD / 4);      // 557056
    const int NW = HIDD  * (QKD / 4);      // 65536
    int gid = blockIdx.x * 256 + threadIdx.x;

    if (gid < NA) {
        int row = gid / (QKD / 4);
        int d   = (gid % (QKD / 4)) * 4;
        float4 x = (row < BATCH * SEQ)
            ? *(const float4*)&keys[row * QKD + d]
            : *(const float4*)&queries[(row - BATCH * SEQ) * QKD + d];
        split4(x, &g_abf[row * 1024 + d], &g_abf[row * 1024 + 512 + d]);
        return;
    }
    gid -= NA;
    if (gid < NW) {
        int n = gid / (QKD / 4);
        int d = (gid % (QKD / 4)) * 4;
        float4 x = *(const float4*)&W1[n * 1024 + QKD + d];
        split4(x, &g_wkbf[n * 1024 + d], &g_wkbf[n * 1024 + 512 + d]);
        return;
    }
    gid -= NW;
    if (gid < NW) {
        int n = gid / (QKD / 4);
        int d = (gid % (QKD / 4)) * 4;
        float4 x = *(const float4*)&W1[n * 1024 + d];
        split4(x, &g_wqbf[n * 1024 + d], &g_wqbf[n * 1024 + 512 + d]);
    }
}

// ---------------------------------------------------------------------------
// Fused projection GEMM via mma.sync bf16 (HMMA), split-K (hi*hi + hi*lo + lo*hi).
// CTA 128x128, 8 warps as 4(m) x 2(n), warp tile 32m x 64n, chunks of K=64,
// 2-stage cp.async pipeline, XOR-swizzled smem + ldmatrix.
// ---------------------------------------------------------------------------
__global__ void __launch_bounds__(256, 1) mma_gemm(const float* __restrict__ b1)
{
    extern __shared__ char dyn_smem[];
    const uint32_t sb = (smem_u32(dyn_smem) + 127u) & ~127u;

    const int tid  = threadIdx.x;
    const int wid  = tid >> 5;
    const int lane = tid & 31;
    const int nt = blockIdx.x;
    const int mt = blockIdx.y;
    const bool is_q = (mt >= 32);
    const int m0 = mt * 128;
    const int n0 = nt * 128;
    const __nv_bfloat16* __restrict__ Bsrc = is_q ? g_wqbf : g_wkbf;

    const int wm = (wid & 3) * 32;     // warp m offset in tile
    const int wn = (wid >> 2) * 64;    // warp n offset in tile

    float acc[2][8][4] = {};

    // ---- async copy of one K-chunk (A 16KB + B 16KB) into buffer c&1 ----
    auto issue = [&](int c) {
        const int seg = c >> 3;
        const int off = (c & 7) * KC;
        const int acol = (seg == 2 ? 512 : 0) + off;   // A-lo on seg 2
        const int bcol = (seg == 1 ? 512 : 0) + off;   // B-lo on seg 1
        const uint32_t aB = sb + (uint32_t)(c & 1) * (2 * CHUNK_BYTES);
        const uint32_t bB = aB + CHUNK_BYTES;
        #pragma unroll
        for (int l = 0; l < 4; ++l) {
            int idx = tid + l * 256;            // 1024 x 16B
            int r = idx >> 3, g = idx & 7;      // row 0..127, 16B group 0..7
            cp16(aB + r * 128 + ((g ^ (r & 7)) << 4),
                 &g_abf[(m0 + r) * 1024 + acol + g * 8]);
        }
        #pragma unroll
        for (int l = 0; l < 4; ++l) {
            int idx = tid + l * 256;
            int r = idx >> 3, g = idx & 7;
            cp16(bB + r * 128 + ((g ^ (r & 7)) << 4),
                 &Bsrc[(n0 + r) * 1024 + bcol + g * 8]);
        }
        cp_commit();
    };

    issue(0);
    issue(1);

    for (int c = 0; c < NCHUNK; ++c) {
        if (c + 1 < NCHUNK) asm volatile("cp.async.wait_group 1;" ::: "memory");
        else                asm volatile("cp.async.wait_group 0;" ::: "memory");
        __syncthreads();

        const uint32_t aB = sb + (uint32_t)(c & 1) * (2 * CHUNK_BYTES);
        const uint32_t bB = aB + CHUNK_BYTES;

        #pragma unroll
        for (int ks = 0; ks < 4; ++ks) {                 // 4 x k16 per chunk
            const int ch = ks * 2 + (lane >> 4);         // 16B chunk index in row
            uint32_t afrag[2][4];
            uint32_t bfrag[8][2];
            #pragma unroll
            for (int ma = 0; ma < 2; ++ma) {
                int row = wm + ma * 16 + (lane & 15);
                ldm4(afrag[ma], aB + row * 128 + ((ch ^ (row & 7)) << 4));
            }
            #pragma unroll
            for (int nb = 0; nb < 4; ++nb) {
                int row = wn + nb * 16 + (lane & 15);
                uint32_t t[4];
                ldm4(t, bB + row * 128 + ((ch ^ (row & 7)) << 4));
                bfrag[2 * nb + 0][0] = t[0]; bfrag[2 * nb + 0][1] = t[2];
                bfrag[2 * nb + 1][0] = t[1]; bfrag[2 * nb + 1][1] = t[3];
            }
            #pragma unroll
            for (int ma = 0; ma < 2; ++ma)
                #pragma unroll
                for (int na = 0; na < 8; ++na)
                    mma16816(acc[ma][na],
                             afrag[ma][0], afrag[ma][1], afrag[ma][2], afrag[ma][3],
                             bfrag[na][0], bfrag[na][1]);
        }
        __syncthreads();
        if (c + 2 < NCHUNK) issue(c + 2);
    }

    // ---- epilogue: registers -> gmem, bias fused for kproj ----
    float* __restrict__ dst = is_q ? g_qproj : g_kproj;
    const int mbase = (is_q ? m0 - BATCH * SEQ : m0) + wm;
    #pragma unroll
    for (int ma = 0; ma < 2; ++ma) {
        int r0 = mbase + ma * 16 + (lane >> 2);
        #pragma unroll
        for (int na = 0; na < 8; ++na) {
            int col = n0 + wn + na * 8 + (lane & 3) * 2;
            float bx = 0.f, by = 0.f;
            if (!is_q) { bx = b1[col]; by = b1[col + 1]; }
            float2 v0 = {acc[ma][na][0] + bx, acc[ma][na][1] + by};
            float2 v1 = {acc[ma][na][2] + bx, acc[ma][na][3] + by};
            *(float2*)&dst[r0 * HIDD + col]       = v0;
            *(float2*)&dst[(r0 + 8) * HIDD + col] = v1;
        }
    }
}

// ---------------------------------------------------------------------------
// Scores: g_attn[b,q,s] = sum_h tanh(qproj[b,q,h] + kproj[b,s,h]) * w2[h]
// ---------------------------------------------------------------------------
__global__ void scores_kernel(const float* __restrict__ w2)
{
    constexpr int QT = 32, ST = 32, HT = 64;
    __shared__ float qs[HT][QT];
    __shared__ float ks[HT][ST];
    __shared__ float w2s[HT];

    const int b  = blockIdx.z;
    const int q0 = blockIdx.y * QT;
    const int s0 = blockIdx.x * ST;
    const int tid = threadIdx.x;      // 128
    const int ts = tid % 16;
    const int tq = tid / 16;

    float acc[4][2] = {};

    for (int h0 = 0; h0 < HIDD; h0 += HT) {
        #pragma unroll
        for (int l = 0; l < 4; ++l) {
            int idx = tid + l * 128;
            int q   = idx / 16;
            int c4  = idx % 16;
            float4 v = *(const float4*)&g_qproj[(b * NQ + q0 + q) * HIDD + h0 + c4 * 4];
            qs[c4 * 4 + 0][q] = v.x;
            qs[c4 * 4 + 1][q] = v.y;
            qs[c4 * 4 + 2][q] = v.z;
            qs[c4 * 4 + 3][q] = v.w;
        }
        #pragma unroll
        for (int l = 0; l < 4; ++l) {
            int idx = tid + l * 128;
            int s   = idx / 16;
            int c4  = idx % 16;
            float4 v = *(const float4*)&g_kproj[(b * SEQ + s0 + s) * HIDD + h0 + c4 * 4];
            ks[c4 * 4 + 0][s] = v.x;
            ks[c4 * 4 + 1][s] = v.y;
            ks[c4 * 4 + 2][s] = v.z;
            ks[c4 * 4 + 3][s] = v.w;
        }
        if (tid < HT) w2s[tid] = w2[h0 + tid];
        __syncthreads();

        #pragma unroll 4
        for (int h = 0; h < HT; ++h) {
            float4 a = *(const float4*)&qs[h][tq * 4];
            float2 k = *(const float2*)&ks[h][ts * 2];
            float  wv = w2s[h];
            float aa[4] = {a.x, a.y, a.z, a.w};
            float kv[2] = {k.x, k.y};
            #pragma unroll
            for (int i = 0; i < 4; ++i)
                #pragma unroll
                for (int j = 0; j < 2; ++j)
                    acc[i][j] += fast_tanh(aa[i] + kv[j]) * wv;
        }
        __syncthreads();
    }

    #pragma unroll
    for (int i = 0; i < 4; ++i) {
        int q = q0 + tq * 4 + i;
        float2 o = {acc[i][0], acc[i][1]};
        *(float2*)&g_attn[(b * NQ + q) * SEQ + s0 + ts * 2] = o;
    }
}

// ---------------------------------------------------------------------------
// Softmax over s (in place on g_attn).
// ---------------------------------------------------------------------------
__global__ void softmax_kernel()
{
    const int row = blockIdx.x;
    float* p = &g_attn[row * SEQ];
    const int tid = threadIdx.x;
    __shared__ float red[128];

    float4 a = *(const float4*)&p[tid * 8];
    float4 c = *(const float4*)&p[tid * 8 + 4];

    float m = fmaxf(fmaxf(fmaxf(a.x, a.y), fmaxf(a.z, a.w)),
                    fmaxf(fmaxf(c.x, c.y), fmaxf(c.z, c.w)));
    red[tid] = m;
    __syncthreads();
    #pragma unroll
    for (int off = 64; off > 0; off >>= 1) {
        if (tid < off) red[tid] = fmaxf(red[tid], red[tid + off]);
        __syncthreads();
    }
    float rowmax = red[0];
    __syncthreads();

    a.x = __expf(a.x - rowmax); a.y = __expf(a.y - rowmax);
    a.z = __expf(a.z - rowmax); a.w = __expf(a.w - rowmax);
    c.x = __expf(c.x - rowmax); c.y = __expf(c.y - rowmax);
    c.z = __expf(c.z - rowmax); c.w = __expf(c.w - rowmax);

    float s = a.x + a.y + a.z + a.w + c.x + c.y + c.z + c.w;
    red[tid] = s;
    __syncthreads();
    #pragma unroll
    for (int off = 64; off > 0; off >>= 1) {
        if (tid < off) red[tid] += red[tid + off];
        __syncthreads();
    }
    float inv = 1.0f / red[0];

    a.x *= inv; a.y *= inv; a.z *= inv; a.w *= inv;
    c.x *= inv; c.y *= inv; c.z *= inv; c.w *= inv;
    *(float4*)&p[tid * 8]     = a;
    *(float4*)&p[tid * 8 + 4] = c;
}

// ---------------------------------------------------------------------------
// Final: out[b,q,v] = sum_s attn[b,q,s] * values[b,s,v]
// ---------------------------------------------------------------------------
__global__ void final_kernel(const float* __restrict__ values,
                             float* __restrict__ out)
{
    constexpr int VT = 16, SC = 32;
    __shared__ float at[SC][NQ];
    __shared__ float vs[SC][VT];

    const int b  = blockIdx.y;
    const int v0 = blockIdx.x * VT;
    const int tid = threadIdx.x;      // 256
    const int tx = tid % 8;
    const int ty = tid / 8;

    float acc[2][2] = {};

    for (int s0 = 0; s0 < SEQ; s0 += SC) {
        #pragma unroll
        for (int l = 0; l < 2; ++l) {
            int idx = tid + l * 256;
            int q   = idx / 8;
            int c4  = idx % 8;
            float4 v = *(const float4*)&g_attn[(b * NQ + q) * SEQ + s0 + c4 * 4];
            at[c4 * 4 + 0][q] = v.x;
            at[c4 * 4 + 1][q] = v.y;
            at[c4 * 4 + 2][q] = v.z;
            at[c4 * 4 + 3][q] = v.w;
        }
        if (tid < 128) {
            int s  = tid / 4;
            int c4 = tid % 4;
            float4 v = *(const float4*)&values[(b * SEQ + s0 + s) * 512 + v0 + c4 * 4];
            *(float4*)&vs[s][c4 * 4] = v;
        }
        __syncthreads();

        #pragma unroll 8
        for (int s = 0; s < SC; ++s) {
            float2 a = *(const float2*)&at[s][ty * 2];
            float2 v = *(const float2*)&vs[s][tx * 2];
            acc[0][0] += a.x * v.x;  acc[0][1] += a.x * v.y;
            acc[1][0] += a.y * v.x;  acc[1][1] += a.y * v.y;
        }
        __syncthreads();
    }

    #pragma unroll
    for (int i = 0; i < 2; ++i) {
        int q = ty * 2 + i;
        float2 o = {acc[i][0], acc[i][1]};
        *(float2*)&out[(b * NQ + q) * 512 + v0 + tx * 2] = o;
    }
}

// ---------------------------------------------------------------------------
extern "C" void kernel_launch(void* const* d_in, const int* in_sizes, int n_in,
                              void* d_out, int out_size)
{
    (void)in_sizes; (void)n_in; (void)out_size;
    const float* queries = (const float*)d_in[0];   // (4,64,512)
    const float* keys    = (const float*)d_in[1];   // (4,1024,512)
    const float* values  = (const float*)d_in[2];   // (4,1024,512)
    const float* W1      = (const float*)d_in[3];   // (512,1024)
    const float* b1      = (const float*)d_in[4];   // (512,)
    const float* w2      = (const float*)d_in[5];   // (512,)
    float* out = (float*)d_out;                     // (4,64,512)

    // bf16 hi/lo split of A (keys||queries) and W slices
    prep_convert<<<2688, 256>>>(queries, keys, W1);

    // fused projections on HMMA (mma.sync bf16, split-K = 1536)
    const int dyn = 2 * 2 * CHUNK_BYTES + 256;      // 64 KB double buffer + align pad
    cudaFuncSetAttribute(mma_gemm, cudaFuncAttributeMaxDynamicSharedMemorySize, dyn);
    mma_gemm<<<dim3(4, MROWS / 128), 256, dyn>>>(b1);

    // scores -> g_attn
    scores_kernel<<<dim3(SEQ / 32, NQ / 32, BATCH), 128>>>(w2);

    // softmax in place
    softmax_kernel<<<BATCH * NQ, 128>>>();

    // out = attn @ values
    final_kernel<<<dim3(512 / 16, BATCH), 256>>>(values, out);
}